// round 10
// baseline (speedup 1.0000x reference)
#include <cuda_runtime.h>

#define BB    32
#define TT    512
#define HH    1024
#define DD    4
#define NBLK  148
#define NTHR  768              // 3 groups x 8 warps
#define NDIAG (TT + DD - 1)    // 515

// Device-global scratch (allocation forbidden)
__device__ float g_h[2][DD][HH / 4][BB][4];   // double-buffered hidden, packed [k/4][m][4]
__device__ float g_xT[TT][HH / 4][BB][4];     // packed transposed input
__device__ unsigned int g_slot[NBLK];         // monotonic barrier slots (replay-safe)

// ---------------------------------------------------------------------------
// Atomic-free grid barrier (one writer per slot; 148 parallel pollers)
// ---------------------------------------------------------------------------
__device__ __forceinline__ void gridbar(unsigned int target) {
    __syncthreads();
    if (threadIdx.x == 0) {
        __threadfence();
        asm volatile("st.global.release.gpu.u32 [%0], %1;"
                     :: "l"(&g_slot[blockIdx.x]), "r"(target) : "memory");
    }
    if (threadIdx.x < NBLK) {
        unsigned int v;
        do {
            asm volatile("ld.acquire.gpu.u32 %0, [%1];"
                         : "=r"(v) : "l"(&g_slot[threadIdx.x]) : "memory");
        } while (v < target);
    }
    __syncthreads();
}

__device__ __forceinline__ void barG(int grp) {
    asm volatile("bar.sync %0, %1;" :: "r"(grp + 1), "r"(256) : "memory");
}

__device__ __forceinline__ int nact_of(int t) {
    int v = ((t & 7) == 0) ? 3 : ((t & 3) == 0) ? 2 : ((t & 1) == 0) ? 1 : 0;
    return (v + 1) << 8;
}

#define FMA4(av, w0)                                                          \
    acc[0] += (av) * (w0).x; acc[1] += (av) * (w0).y;                         \
    acc[2] += (av) * (w0).z; acc[3] += (av) * (w0).w;
#define FMA8(av, w0, w1)                                                      \
    FMA4(av, w0)                                                              \
    acc[4] += (av) * (w1).x; acc[5] += (av) * (w1).y;                         \
    acc[6] += (av) * (w1).z; acc[7] += (av) * (w1).w;

// ---------------------------------------------------------------------------
// acc[c] += sum_{k in [k0,k0+kn)} A[k][lane] * W[k][col0+c], c = 0..CT-1
// A packed [k/4][32][4], .cg (L2-only; keeps L1 for W). W .ca (L1-resident,
// static per-SM ownership). kn is a multiple of 4.
// ---------------------------------------------------------------------------
template<int CT>
__device__ __forceinline__ void dotseg(const float* __restrict__ Apack,
                                       const float* __restrict__ W,
                                       int k0, int kn, int lane, float* acc) {
    const float4* Ap = (const float4*)(Apack + (k0 >> 2) * (BB * 4) + lane * 4);
    const float4* Wp = (const float4*)(W + (size_t)k0 * HH);
#pragma unroll 2
    for (int kk = 0; kk < kn; kk += 4) {
        float4 a = __ldcg(Ap); Ap += BB;
        float4 w0, w1;
        if (CT == 4) {
            w0 = __ldg(Wp);       FMA4(a.x, w0);
            w0 = __ldg(Wp + 256); FMA4(a.y, w0);
            w0 = __ldg(Wp + 512); FMA4(a.z, w0);
            w0 = __ldg(Wp + 768); FMA4(a.w, w0);
        } else {
            w0 = __ldg(Wp);       w1 = __ldg(Wp + 1);   FMA8(a.x, w0, w1);
            w0 = __ldg(Wp + 256); w1 = __ldg(Wp + 257); FMA8(a.y, w0, w1);
            w0 = __ldg(Wp + 512); w1 = __ldg(Wp + 513); FMA8(a.z, w0, w1);
            w0 = __ldg(Wp + 768); w1 = __ldg(Wp + 769); FMA8(a.w, w0, w1);
        }
        Wp += 1024;
    }
}

// ---------------------------------------------------------------------------
// One CT-column GEMM tile of stage (t,d), run by one 8-warp group.
// ---------------------------------------------------------------------------
template<int CT>
__device__ __forceinline__ void gemm_tile(int t, int d, int col0, int recK,
                                          int bufR, int bufW,
                                          const float* __restrict__ Wx0,
                                          const float* __restrict__ Wxd,
                                          const float* __restrict__ Wh,
                                          const float* __restrict__ bias,
                                          float* __restrict__ out,
                                          float (*red)[256], int tg, int grp) {
    const int lane = tg & 31;
    const int wid  = tg >> 5;

    const float* A1 = (d == 0) ? &g_xT[t - 1][0][0][0] : &g_h[bufR][d - 1][0][0][0];
    const float* hR = &g_h[bufR][d][0][0][0];
    const float* Wx = ((d == 0) ? Wx0 : Wxd + (size_t)(d - 1) * HH * HH) + col0;
    const float* Wr = Wh + (size_t)d * HH * HH + col0;

    float acc[CT];
#pragma unroll
    for (int c = 0; c < CT; ++c) acc[c] = 0.f;

    dotseg<CT>(A1, Wx, wid * 128, 128, lane, acc);        // FF: K=1024 / 8 warps
    const int base = HH - recK;                            // 256*g
    const int rs   = recK >> 3;
    dotseg<CT>(hR, Wr, base + wid * rs, rs, lane, acc);   // recurrent, masked rows

#pragma unroll
    for (int c = 0; c < CT; ++c) red[wid][lane * CT + c] = acc[c];
    barG(grp);

    if (tg < CT * 32) {
        const int c = tg & (CT - 1);
        const int m = tg / CT;
        float s = 0.f;
#pragma unroll
        for (int w = 0; w < 8; ++w) s += red[w][tg];
        const int   col = col0 + c;
        const float h   = tanhf(s + __ldg(bias + d * HH + col));
        g_h[bufW][d][col >> 2][m][col & 3] = h;
        out[(((size_t)m * TT + (t - 1)) * DD + d) * HH + col] = h;
    }
    barG(grp);
}

// Inactive 64-column tile: carry h(t-1), write out.
__device__ __forceinline__ void copy_tile(int t, int d, int col0, int bufR, int bufW,
                                          float* __restrict__ out, int tg) {
    const float4* src = (const float4*)&g_h[bufR][d][col0 >> 2][0][0];
    float4*       dst = (float4*)&g_h[bufW][d][col0 >> 2][0][0];
#pragma unroll
    for (int i = tg; i < 16 * BB; i += 256) {
        const int c4 = i >> 5, m = i & 31;
        float4 v = __ldcg(src + c4 * BB + m);
        dst[c4 * BB + m] = v;
        *(float4*)(out + (((size_t)m * TT + (t - 1)) * DD + d) * HH + col0 + c4 * 4) = v;
    }
}

// copy id -> (d, col0) for diagonal s
__device__ __forceinline__ bool copy_decode(int cid, int s, int& dd, int& col0) {
#pragma unroll
    for (int d = 0; d < DD; ++d) {
        const int t = s - d;
        if (t >= 1 && t <= TT) {
            const int na = nact_of(t);
            const int nc = (HH - na) >> 6;
            if (cid < nc) { dd = d; col0 = na + (cid << 6); return true; }
            cid -= nc;
        }
    }
    return false;
}

// ---------------------------------------------------------------------------
// Persistent wavefront kernel. Static hand-balanced schedule per block b:
//   b in [0,32):    { g2 bundle(8col, d=s&3), g1 unit 2b, g1 unit 2b+1 }
//   b in [32,64):   { g3 bundle(8col, d=s&7<4), g0 unit 2(b-32), +1 }
//   b in [64,128):  { g0 units 64+3(b-64)+q }
//   b in [128,132): { g1 units 64+3(b-128)+q, g1 unit 124+(b-128), 2 copies }
//   b in [132,148): { g1 units 64+3(b-128)+q, 2 copies }
// g0 unit u: d=u>>6, col0=4*(u&63), recK=1024 (active every diagonal)
// g1 unit u: d=2*(u>>6)+(s&1), col0=256+4*(u&63), recK=768
// ---------------------------------------------------------------------------
__global__ void __launch_bounds__(NTHR, 1)
cwrnn_kernel(const float* __restrict__ Wx0, const float* __restrict__ Wxd,
             const float* __restrict__ Wh, const float* __restrict__ bias,
             float* __restrict__ out) {
    __shared__ float red[3][8][256];
    const int tid = threadIdx.x;
    const int bid = blockIdx.x;
    const int grp = tid >> 8;        // 0..2
    const int tg  = tid & 255;

    const unsigned int barbase = g_slot[bid];
    unsigned int r = 1;

    {   // zero both h buffers
        float* hz = &g_h[0][0][0][0][0];
        for (int i = bid * NTHR + tid; i < 2 * DD * HH * BB; i += NBLK * NTHR)
            hz[i] = 0.f;
    }
    gridbar(barbase + r); ++r;

    const int nq = (bid < 128) ? 3 : ((bid < 132) ? 6 : 5);

    for (int s = 1; s <= NDIAG; ++s) {
        const int bufR = (s - 1) & 1;
        const int bufW = s & 1;

        for (int q = grp; q < nq; q += 3) {
            if (bid < 32) {
                if (q == 0) {
                    const int d = s & 3, t = s - d;
                    if (t >= 1 && t <= TT)
                        gemm_tile<8>(t, d, 512 + 8 * bid, 512, bufR, bufW,
                                     Wx0, Wxd, Wh, bias, out, red[grp], tg, grp);
                } else {
                    const int u = 2 * bid + (q - 1);           // p=0
                    const int d = s & 1, t = s - d;
                    if (t >= 1 && t <= TT)
                        gemm_tile<4>(t, d, 256 + 4 * (u & 63), 768, bufR, bufW,
                                     Wx0, Wxd, Wh, bias, out, red[grp], tg, grp);
                }
            } else if (bid < 64) {
                if (q == 0) {
                    const int d = s & 7;
                    if (d < 4) {
                        const int t = s - d;
                        if (t >= 1 && t <= TT)
                            gemm_tile<8>(t, d, 768 + 8 * (bid - 32), 256, bufR, bufW,
                                         Wx0, Wxd, Wh, bias, out, red[grp], tg, grp);
                    }
                } else {
                    const int u = 2 * (bid - 32) + (q - 1);    // g0, d=0
                    const int t = s;
                    if (t <= TT)
                        gemm_tile<4>(t, 0, 4 * (u & 63), 1024, bufR, bufW,
                                     Wx0, Wxd, Wh, bias, out, red[grp], tg, grp);
                }
            } else if (bid < 128) {
                const int u = 64 + 3 * (bid - 64) + q;         // g0, d=1..3
                const int d = u >> 6, t = s - d;
                if (t >= 1 && t <= TT)
                    gemm_tile<4>(t, d, 4 * (u & 63), 1024, bufR, bufW,
                                 Wx0, Wxd, Wh, bias, out, red[grp], tg, grp);
            } else {
                const bool four = (bid < 132);
                const int ngemm = four ? 4 : 3;
                if (q < ngemm) {
                    const int u = (q < 3) ? 64 + 3 * (bid - 128) + q
                                          : 124 + (bid - 128);  // p=1
                    const int d = 2 + (s & 1), t = s - d;
                    if (t >= 1 && t <= TT)
                        gemm_tile<4>(t, d, 256 + 4 * (u & 63), 768, bufR, bufW,
                                     Wx0, Wxd, Wh, bias, out, red[grp], tg, grp);
                } else {
                    const int cid = four ? 2 * (bid - 128) + (q - 4)
                                         : 8 + 2 * (bid - 132) + (q - 3);
                    int dd, col0;
                    if (copy_decode(cid, s, dd, col0))
                        copy_tile(s - dd, dd, col0, bufR, bufW, out, tg);
                }
            }
        }
        gridbar(barbase + r); ++r;
    }
}

// ---------------------------------------------------------------------------
// x [B][T][DIN] -> packed g_xT[t][k/4][m][4]
// ---------------------------------------------------------------------------
__global__ void xT_kernel(const float* __restrict__ x) {
    int idx = blockIdx.x * blockDim.x + threadIdx.x;
    if (idx >= TT * (HH / 4) * BB) return;
    const int k4 = idx & 255;
    const int m  = (idx >> 8) & 31;
    const int t  = idx >> 13;
    float4 v = *(const float4*)(x + ((size_t)m * TT + t) * HH + k4 * 4);
    *(float4*)(&g_xT[t][k4][m][0]) = v;
}

// ---------------------------------------------------------------------------
// kernel_launch: graph-capturable, allocation-free
// ---------------------------------------------------------------------------
extern "C" void kernel_launch(void* const* d_in, const int* in_sizes, int n_in,
                              void* d_out, int out_size) {
    const float* x   = (const float*)d_in[0];
    const float* Wx0 = (const float*)d_in[1];
    const float* Wxd = (const float*)d_in[2];
    const float* Wh  = (const float*)d_in[3];
    const float* b   = (const float*)d_in[4];
    float* out = (float*)d_out;

    xT_kernel<<<(TT * (HH / 4) * BB + 255) / 256, 256>>>(x);
    cwrnn_kernel<<<NBLK, NTHR>>>(Wx0, Wxd, Wh, b, out);
}

// round 12
// speedup vs baseline: 1.6460x; 1.6460x over previous
#include <cuda_runtime.h>

#define BB    32
#define TT    512
#define HH    1024
#define DD    4
#define NBLK  148
#define NTHR  512              // 16 warps, K split 16 ways
#define NDIAG (TT + DD - 1)    // 515

#define HB    (DD * HH * BB)   // one h buffer
#define RECROWS 40960          // per-depth packed rec rows: 16*(1024+768+512+256)

// Device-global scratch (allocation forbidden)
__device__ float g_h[2 * HB + 16];                 // double-buffered hidden, [buf][d][k][m]
__device__ float g_x[TT * HH * BB];                // [t][k][m]
__device__ float g_wff[DD * 64 * HH * 16];         // packed FF weights [d][jt][k][16]
__device__ float g_wrec[DD * RECROWS * 16];        // packed rec weights [d][tile rows][16]
__device__ unsigned int g_slot[NBLK];              // monotonic barrier slots (replay-safe)

// rec-tile row prefix within a depth: tiles ordered j=0..63, group g=j>>4 has 1024-256g rows
__device__ __forceinline__ int rec_pre(int j) {
    const int g = j >> 4, u = j & 15;
    const int baseG[4] = {0, 16384, 28672, 36864};
    return baseG[g] + u * (1024 - 256 * g);
}

// ---------------------------------------------------------------------------
// Atomic-free grid barrier (one writer per slot; 148 parallel pollers)
// ---------------------------------------------------------------------------
__device__ __forceinline__ void gridbar(unsigned int target) {
    __syncthreads();
    if (threadIdx.x == 0) {
        __threadfence();
        asm volatile("st.global.release.gpu.u32 [%0], %1;"
                     :: "l"(&g_slot[blockIdx.x]), "r"(target) : "memory");
    }
    if (threadIdx.x < NBLK) {
        unsigned int v;
        do {
            asm volatile("ld.acquire.gpu.u32 %0, [%1];"
                         : "=r"(v) : "l"(&g_slot[threadIdx.x]) : "memory");
        } while (v < target);
    }
    __syncthreads();
}

__device__ __forceinline__ int nact_of(int t) {
    int v = ((t & 7) == 0) ? 3 : ((t & 3) == 0) ? 2 : ((t & 1) == 0) ? 1 : 0;
    return (v + 1) << 8;
}

// acc[ci*4+mi] += av[mi] * wv[ci]  (inline function: no macro token capture)
__device__ __forceinline__ void fma16(float* acc, float4 av, float4 wv) {
    acc[0]  += av.x * wv.x; acc[1]  += av.y * wv.x;
    acc[2]  += av.z * wv.x; acc[3]  += av.w * wv.x;
    acc[4]  += av.x * wv.y; acc[5]  += av.y * wv.y;
    acc[6]  += av.z * wv.y; acc[7]  += av.w * wv.y;
    acc[8]  += av.x * wv.z; acc[9]  += av.y * wv.z;
    acc[10] += av.z * wv.z; acc[11] += av.w * wv.z;
    acc[12] += av.x * wv.w; acc[13] += av.y * wv.w;
    acc[14] += av.z * wv.w; acc[15] += av.w * wv.w;
}

// ---------------------------------------------------------------------------
// Register outer-product dot: 4m x 4c per thread (warp: 32m x 16c).
// A: [k][32] dense line per k (.cg — L2, produced cross-SM).
// W16: packed [k][16] (.ca — L1-resident per static ownership).
// Distance-2 software pipeline to cover L2 latency. kn >= 16.
// ---------------------------------------------------------------------------
__device__ __forceinline__ void dot16(const float* __restrict__ A, int ak0,
                                      const float* __restrict__ W16, int wk0,
                                      int kn, int mg, int cg, float* acc) {
    const float4* Ap = (const float4*)A + ak0 * 8 + mg;
    const float4* Wp = (const float4*)W16 + wk0 * 4 + cg;
    float4 a0 = __ldcg(Ap);     float4 w0 = __ldg(Wp);
    float4 a1 = __ldcg(Ap + 8); float4 w1 = __ldg(Wp + 4);
#pragma unroll 4
    for (int k = 0; k < kn - 2; ++k) {
        float4 a2 = __ldcg(Ap + 16);
        float4 w2 = __ldg(Wp + 8);
        fma16(acc, a0, w0);
        a0 = a1; a1 = a2; w0 = w1; w1 = w2;
        Ap += 8; Wp += 4;
    }
    fma16(acc, a0, w0);
    fma16(acc, a1, w1);
}

// ---------------------------------------------------------------------------
// One 16-col tile of stage (t,d): whole block (16 warps, K split 16 ways).
// ---------------------------------------------------------------------------
__device__ __forceinline__ void gemm_tile(int t, int d, int jt, int g,
                                          int bufR, int bufW,
                                          const float* __restrict__ bias,
                                          float* __restrict__ out,
                                          float (*red)[512], int tid) {
    const int lane = tid & 31;
    const int w    = tid >> 5;          // 0..15
    const int mg   = lane & 7;
    const int cg   = lane >> 3;
    const int col0 = jt << 4;

    const float* A1  = (d == 0) ? g_x + (size_t)(t - 1) * HH * BB
                                : g_h + (size_t)bufR * HB + (size_t)(d - 1) * HH * BB;
    const float* hR  = g_h + (size_t)bufR * HB + (size_t)d * HH * BB;
    const float* wff = g_wff + ((size_t)(d * 64 + jt) * HH) * 16;
    const float* wrc = g_wrec + ((size_t)d * RECROWS + rec_pre(jt)) * 16;

    float acc[16];
#pragma unroll
    for (int i = 0; i < 16; ++i) acc[i] = 0.f;

    // feed-forward: K=1024, 64 rows per warp
    dot16(A1, 64 * w, wff, 64 * w, 64, mg, cg, acc);
    // recurrent: rows [256g, 1024), (64-16g) rows per warp
    const int rs = 64 - 16 * g;
    dot16(hR, (g << 8) + rs * w, wrc, rs * w, rs, mg, cg, acc);

    // stash partials: red[w][c*32 + m] as float4 over m
    float4* rp = (float4*)&red[w][0];
#pragma unroll
    for (int ci = 0; ci < 4; ++ci)
        rp[(4 * cg + ci) * 8 + mg] =
            make_float4(acc[ci * 4 + 0], acc[ci * 4 + 1],
                        acc[ci * 4 + 2], acc[ci * 4 + 3]);
    __syncthreads();

    if (tid < 128) {
        const int c  = tid >> 3;
        const int m0 = (tid & 7) * 4;
        float4 s = make_float4(0.f, 0.f, 0.f, 0.f);
#pragma unroll
        for (int ww = 0; ww < 16; ++ww) {
            float4 v = ((float4*)&red[ww][0])[c * 8 + (tid & 7)];
            s.x += v.x; s.y += v.y; s.z += v.z; s.w += v.w;
        }
        const int   col = col0 + c;
        const float bv  = __ldg(bias + d * HH + col);
        float4 h4 = make_float4(tanhf(s.x + bv), tanhf(s.y + bv),
                                tanhf(s.z + bv), tanhf(s.w + bv));
        *(float4*)(g_h + (size_t)bufW * HB + (size_t)d * HH * BB + col * BB + m0) = h4;
        const size_t mstride = (size_t)TT * DD * HH;
        size_t ob = ((size_t)m0 * TT + (t - 1)) * DD * HH + d * HH + col;
        out[ob] = h4.x; out[ob + mstride] = h4.y;
        out[ob + 2 * mstride] = h4.z; out[ob + 3 * mstride] = h4.w;
    }
    __syncthreads();
}

// Inactive 128-col tile: carry h(t-1), write out.
__device__ __forceinline__ void copy_tile(int t, int d, int col0,
                                          int bufR, int bufW,
                                          float* __restrict__ out, int tid) {
    const float* hR = g_h + (size_t)bufR * HB + (size_t)d * HH * BB;
    float*       hW = g_h + (size_t)bufW * HB + (size_t)d * HH * BB;
    const size_t mstride = (size_t)TT * DD * HH;
#pragma unroll
    for (int i = tid; i < 1024; i += NTHR) {
        const int col = col0 + (i >> 3);
        const int mg  = i & 7;
        float4 v = __ldcg((const float4*)(hR + col * BB) + mg);
        *((float4*)(hW + col * BB) + mg) = v;
        size_t ob = ((size_t)(4 * mg) * TT + (t - 1)) * DD * HH + d * HH + col;
        out[ob] = v.x; out[ob + mstride] = v.y;
        out[ob + 2 * mstride] = v.z; out[ob + 3 * mstride] = v.w;
    }
}

// ---------------------------------------------------------------------------
// Persistent wavefront kernel. Static ownership (L1-resident packed W):
//   b 0..63   : g0 tile, d=b>>4, jt=b&15           (active when t valid)
//   b 64..95  : g1 tile, d=2*((b-64)>>4)+(s&1), jt=16+((b-64)&15)
//   b 96..111 : g2 tile, d=s&3, jt=32+(b-96)
//   b 112..127: g3 tile, d=s&7 (<4), jt=48+(b-112)
//   b 128..147: copy tiles (<=18/diagonal)
// ---------------------------------------------------------------------------
__global__ void __launch_bounds__(NTHR, 1)
cwrnn_kernel(const float* __restrict__ bias, float* __restrict__ out) {
    __shared__ float red[16][512];
    const int tid = threadIdx.x;
    const int bid = blockIdx.x;

    const unsigned int barbase = g_slot[bid];
    unsigned int r = 1;

    {   // zero both h buffers
        float4* hz = (float4*)g_h;
        for (int i = bid * NTHR + tid; i < (2 * HB) / 4; i += NBLK * NTHR)
            hz[i] = make_float4(0.f, 0.f, 0.f, 0.f);
    }
    gridbar(barbase + r); ++r;

    for (int s = 1; s <= NDIAG; ++s) {
        const int bufR = (s - 1) & 1;
        const int bufW = s & 1;

        if (bid < 128) {
            int d = -1, jt = 0, g = 0;
            if (bid < 64)      { g = 0; d = bid >> 4; jt = bid & 15; }
            else if (bid < 96) { g = 1; const int q = bid - 64;
                                 d = 2 * (q >> 4) + (s & 1); jt = 16 + (q & 15); }
            else if (bid < 112){ g = 2; d = s & 3; jt = 32 + (bid - 96); }
            else               { g = 3; d = s & 7; jt = 48 + (bid - 112); }
            const int t = s - d;
            if (d >= 0 && d < 4 && t >= 1 && t <= TT)
                gemm_tile(t, d, jt, g, bufR, bufW, bias, out, red, tid);
        } else {
            int cid = bid - 128;
            int done = 0;
#pragma unroll
            for (int d = 0; d < DD; ++d) {
                const int t = s - d;
                if (!done && t >= 1 && t <= TT) {
                    const int na = nact_of(t);
                    const int nc = (HH - na) >> 7;
                    if (cid < nc) {
                        copy_tile(t, d, na + (cid << 7), bufR, bufW, out, tid);
                        done = 1;
                    } else cid -= nc;
                }
            }
        }
        gridbar(barbase + r); ++r;
    }
}

// ---------------------------------------------------------------------------
// x [B][T][DIN] -> g_x[t][k][m]  (SMEM-tiled transpose, conflict-free)
// ---------------------------------------------------------------------------
__global__ void xT_kernel(const float* __restrict__ x) {
    __shared__ float sxy[32][33];
    const int t  = blockIdx.x >> 5;
    const int k0 = (blockIdx.x & 31) << 5;
    const int tid = threadIdx.x;
    {   // load 32m x 32k
        const int m  = tid >> 3;
        const int kq = tid & 7;
        float4 v = *(const float4*)(x + ((size_t)m * TT + t) * HH + k0 + kq * 4);
        sxy[m][kq * 4 + 0] = v.x; sxy[m][kq * 4 + 1] = v.y;
        sxy[m][kq * 4 + 2] = v.z; sxy[m][kq * 4 + 3] = v.w;
    }
    __syncthreads();
    {   // store transposed
        const int k  = tid >> 3;
        const int mq = tid & 7;
        float4 v = make_float4(sxy[mq * 4 + 0][k], sxy[mq * 4 + 1][k],
                               sxy[mq * 4 + 2][k], sxy[mq * 4 + 3][k]);
        *(float4*)(g_x + ((size_t)t * HH + k0 + k) * BB + mq * 4) = v;
    }
}

// ---------------------------------------------------------------------------
// Pack FF weights: g_wff[d][jt][k][16] = Wx_d[k][jt*16+c]
// ---------------------------------------------------------------------------
__global__ void packff_kernel(const float* __restrict__ Wx0,
                              const float* __restrict__ Wxd) {
    const int idx = blockIdx.x * blockDim.x + threadIdx.x;   // 4M threads
    if (idx >= DD * 64 * HH * 16) return;
    const int d  = idx >> 20;
    const int rl = idx & ((1 << 20) - 1);
    const int jt = rl >> 14;
    const int k  = (rl >> 4) & 1023;
    const int c  = rl & 15;
    const float* src = (d == 0) ? Wx0 : Wxd + (size_t)(d - 1) * HH * HH;
    g_wff[idx] = src[(size_t)k * HH + jt * 16 + c];
}

// ---------------------------------------------------------------------------
// Pack rec weights: tile (d, j): rows k in [256g, 1024), cols j*16..+16
// ---------------------------------------------------------------------------
__global__ void packrec_kernel(const float* __restrict__ Wh) {
    const int d = blockIdx.x >> 6;
    const int j = blockIdx.x & 63;
    const int g = j >> 4;
    const int rows = 1024 - 256 * g;
    const int pre  = rec_pre(j);
    float* dst = g_wrec + ((size_t)d * RECROWS + pre) * 16;
    const float* src = Wh + (size_t)d * HH * HH + (size_t)(256 * g) * HH + j * 16;
    for (int i = threadIdx.x; i < rows * 16; i += blockDim.x) {
        const int rr = i >> 4, c = i & 15;
        dst[i] = src[(size_t)rr * HH + c];
    }
}

// ---------------------------------------------------------------------------
// kernel_launch: graph-capturable, allocation-free
// ---------------------------------------------------------------------------
extern "C" void kernel_launch(void* const* d_in, const int* in_sizes, int n_in,
                              void* d_out, int out_size) {
    const float* x   = (const float*)d_in[0];
    const float* Wx0 = (const float*)d_in[1];
    const float* Wxd = (const float*)d_in[2];
    const float* Wh  = (const float*)d_in[3];
    const float* b   = (const float*)d_in[4];
    float* out = (float*)d_out;

    xT_kernel<<<TT * 32, 256>>>(x);
    packff_kernel<<<(DD * 64 * HH * 16 + 255) / 256, 256>>>(Wx0, Wxd);
    packrec_kernel<<<DD * 64, 256>>>(Wh);
    cwrnn_kernel<<<NBLK, NTHR>>>(b, out);
}